// round 13
// baseline (speedup 1.0000x reference)
#include <cuda_runtime.h>
#include <cuda_fp16.h>
#include <cstdint>
#include <cstddef>

// Problem dims (fixed by the reference)
#define T_DIM 64
#define B_DIM 256
#define D_DIM 1024
#define H_DIM 1024
#define F_DIM 1024
#define L_DIM 2
#define K_DIM 1024
#define G4    (4 * H_DIM)
#define NGRP  4                // independent barrier groups (one per m0 tile)
#define NCTA_GRP 32            // CTAs per group (j0 slices)

#define SROWH 72               // smem row stride in halves (BK=64 + pad 8)
#define SROWS 136              // smem row stride in halves (BK=128 + pad 8) [step kernel]

// ---------------------------------------------------------------------------
// Scratch (device globals -- allocation-free per harness rules).
// NEVER pass these as kernel args from host (host sees the shadow symbol; ATS
// makes that silently "work" while the device reads zeros). Device-side only.
// ---------------------------------------------------------------------------
__device__ float  g_G[(size_t)T_DIM * B_DIM * G4];       // pregates (268 MB)
__device__ float  g_FB[(size_t)B_DIM * G4];              // features @ Wfh^T + b
__device__ __half g_h16[2][(size_t)B_DIM * H_DIM];       // fp16 hidden (mma operand)
__device__ __half g_mid16[(size_t)T_DIM * B_DIM * H_DIM];// layer-0 outputs (fp16)
__device__ __half g_x16[(size_t)T_DIM * B_DIM * D_DIM];  // x in fp16
__device__ __half g_feat16[(size_t)B_DIM * F_DIM];
__device__ __half g_Wih16[(size_t)L_DIM * G4 * D_DIM];
__device__ __half g_Whh16[(size_t)L_DIM * G4 * H_DIM];
__device__ __half g_Wfh16[(size_t)L_DIM * G4 * F_DIM];
__device__ int    g_len_is64;
__device__ unsigned g_bar_cnt[NGRP];                     // per-group barrier
__device__ unsigned g_bar_gen[NGRP];

// ---------------------------------------------------------------------------
// helpers
// ---------------------------------------------------------------------------
__device__ __forceinline__ void mma_f16(float c[4],
                                        uint32_t a0, uint32_t a1, uint32_t a2, uint32_t a3,
                                        uint32_t b0, uint32_t b1) {
    asm volatile(
        "mma.sync.aligned.m16n8k16.row.col.f32.f16.f16.f32 "
        "{%0,%1,%2,%3}, {%4,%5,%6,%7}, {%8,%9}, {%0,%1,%2,%3};"
        : "+f"(c[0]), "+f"(c[1]), "+f"(c[2]), "+f"(c[3])
        : "r"(a0), "r"(a1), "r"(a2), "r"(a3), "r"(b0), "r"(b1));
}

__device__ __forceinline__ void ldsm_x4(uint32_t& r0, uint32_t& r1,
                                        uint32_t& r2, uint32_t& r3, uint32_t addr) {
    asm volatile("ldmatrix.sync.aligned.m8n8.x4.shared.b16 {%0,%1,%2,%3}, [%4];"
                 : "=r"(r0), "=r"(r1), "=r"(r2), "=r"(r3) : "r"(addr));
}
__device__ __forceinline__ void ldsm_x2(uint32_t& r0, uint32_t& r1, uint32_t addr) {
    asm volatile("ldmatrix.sync.aligned.m8n8.x2.shared.b16 {%0,%1}, [%2];"
                 : "=r"(r0), "=r"(r1) : "r"(addr));
}

__device__ __forceinline__ float sigf(float x) { return 1.0f / (1.0f + __expf(-x)); }

__device__ __forceinline__ void cp_async16(uint32_t saddr, const void* g) {
    asm volatile("cp.async.cg.shared.global [%0], [%1], 16;" :: "r"(saddr), "l"(g));
}
__device__ __forceinline__ void cp_commit() { asm volatile("cp.async.commit_group;"); }
template <int N>
__device__ __forceinline__ void cp_wait() { asm volatile("cp.async.wait_group %0;" :: "n"(N)); }

// ---------------------------------------------------------------------------
// fp32 -> fp16 conversion. dst selected BY ID; pointer resolved in device code.
// ---------------------------------------------------------------------------
__global__ __launch_bounds__(256) void cvt_f16_kernel(const float* __restrict__ s,
                                                      int dst_id, size_t n4) {
    __half* d;
    switch (dst_id) {
        case 0: d = g_x16;    break;
        case 1: d = g_feat16; break;
        case 2: d = g_Wih16;  break;
        case 3: d = g_Whh16;  break;
        default: d = g_Wfh16; break;
    }
    __half2* d2 = reinterpret_cast<__half2*>(d);
    for (size_t i = blockIdx.x * 256ull + threadIdx.x; i < n4;
         i += (size_t)gridDim.x * 256ull) {
        float4 v = reinterpret_cast<const float4*>(s)[i];
        d2[i * 2]     = __floats2half2_rn(v.x, v.y);
        d2[i * 2 + 1] = __floats2half2_rn(v.z, v.w);
    }
}

// ---------------------------------------------------------------------------
// length dtype probe
// ---------------------------------------------------------------------------
__global__ void detect_len_kernel(const int* __restrict__ L) {
    if (threadIdx.x == 0) {
        int any = 0;
        for (int i = 1; i < 256; i += 2) any |= L[i];
        g_len_is64 = (any == 0) ? 1 : 0;
    }
}

// ---------------------------------------------------------------------------
// FB = features @ Wfh_l^T + b_l      (M=256, N=4096). 256 thr, BM=64, BN=128,
// BK=64, ST=2 (two-sync pattern; small kernel, leave as-is).
// ---------------------------------------------------------------------------
__global__ __launch_bounds__(256, 2) void fb_kernel(int l, const float* __restrict__ bias_l) {
    constexpr int BM = 64, BN = 128, BK = 64, NK = K_DIM / BK, ST = 2;
    extern __shared__ __half smem_h[];
    __half* As = smem_h;
    __half* Ws = smem_h + ST * BM * SROWH;

    const __half* A = g_feat16;
    const __half* W = g_Wfh16 + (size_t)l * G4 * F_DIM;

    const int tid  = threadIdx.x;
    const int lane = tid & 31;
    const int warp = tid >> 5;
    const int wm   = (warp >> 2) * (BM / 2);
    const int wn   = (warp & 3) * (BN / 4);
    const int m0   = blockIdx.y * BM;
    const int n0   = blockIdx.x * BN;

    const int a_row  = wm + (lane & 15);
    const int a_koff = (lane >> 4) * 8;
    const int l16    = lane & 15;
    const int b_row  = wn + (l16 & 7);
    const int b_koff = (l16 >> 3) * 8;

    float acc[2][4][4];
#pragma unroll
    for (int im = 0; im < 2; im++)
#pragma unroll
        for (int in = 0; in < 4; in++)
#pragma unroll
            for (int q = 0; q < 4; q++) acc[im][in][q] = 0.0f;

    const uint32_t As_s = (uint32_t)__cvta_generic_to_shared(As);
    const uint32_t Ws_s = (uint32_t)__cvta_generic_to_shared(Ws);

    auto load_stage = [&](int ki, int s) {
#pragma unroll
        for (int i = 0; i < 2; i++) {
            int li = tid + i * 256, row = li >> 3, c8 = (li & 7) * 8;
            cp_async16(As_s + (uint32_t)(((s * BM + row) * SROWH + c8) * 2),
                       A + (size_t)(m0 + row) * K_DIM + ki * BK + c8);
        }
#pragma unroll
        for (int i = 0; i < 4; i++) {
            int li = tid + i * 256, row = li >> 3, c8 = (li & 7) * 8;
            cp_async16(Ws_s + (uint32_t)(((s * BN + row) * SROWH + c8) * 2),
                       W + (size_t)(n0 + row) * K_DIM + ki * BK + c8);
        }
    };

    load_stage(0, 0); cp_commit();

    for (int k = 0; k < NK; k++) {
        if (k + 1 < NK) load_stage(k + 1, (k + 1) & 1);
        cp_commit();
        cp_wait<1>();
        __syncthreads();

        const uint32_t as_s = As_s + (uint32_t)((k & 1) * BM * SROWH * 2);
        const uint32_t ws_s = Ws_s + (uint32_t)((k & 1) * BN * SROWH * 2);
#pragma unroll
        for (int ks = 0; ks < BK; ks += 16) {
            uint32_t af[2][4];
            uint32_t bf[4][2];
#pragma unroll
            for (int im = 0; im < 2; im++)
                ldsm_x4(af[im][0], af[im][1], af[im][2], af[im][3],
                        as_s + (uint32_t)((((a_row + im * 16) * SROWH) + ks + a_koff) * 2));
#pragma unroll
            for (int in = 0; in < 4; in++)
                ldsm_x2(bf[in][0], bf[in][1],
                        ws_s + (uint32_t)((((b_row + in * 8) * SROWH) + ks + b_koff) * 2));
#pragma unroll
            for (int im = 0; im < 2; im++)
#pragma unroll
                for (int in = 0; in < 4; in++)
                    mma_f16(acc[im][in],
                            af[im][0], af[im][1], af[im][2], af[im][3],
                            bf[in][0], bf[in][1]);
        }
        __syncthreads();
    }

    const int wme = wm + (lane >> 2);
    const int wne = wn + (lane & 3) * 2;
#pragma unroll
    for (int im = 0; im < 2; im++)
#pragma unroll
        for (int in = 0; in < 4; in++) {
            int r0 = m0 + wme + im * 16;
            int c  = n0 + wne + in * 8;
            g_FB[(size_t)r0 * G4 + c]           = acc[im][in][0] + bias_l[c];
            g_FB[(size_t)r0 * G4 + c + 1]       = acc[im][in][1] + bias_l[c + 1];
            g_FB[(size_t)(r0 + 8) * G4 + c]     = acc[im][in][2] + bias_l[c];
            g_FB[(size_t)(r0 + 8) * G4 + c + 1] = acc[im][in][3] + bias_l[c + 1];
        }
}

// ---------------------------------------------------------------------------
// G = inp @ Wih_l^T + FB[b]   (M=16384, N=4096);  b = row & 255.
// NEW: BM=256 x BN=128 CTA tile, 512 threads (4x4 warp grid, warp tile 64x32),
// BK=64, ST=3, ONE sync per k-block (same accounting as the step kernel).
// smem = 3*(256+128)*SROWH*2 = 165888 B -> 1 CTA/SM, 16 warps.
// ---------------------------------------------------------------------------
template <bool USE_MID>
__global__ __launch_bounds__(512, 1) void g_kernel(int l) {
    constexpr int BM = 256, BN = 128, BK = 64, NK = K_DIM / BK, ST = 3;
    extern __shared__ __half smem_h[];
    __half* As = smem_h;                         // ST * 256 * SROWH halves
    __half* Ws = smem_h + ST * BM * SROWH;       // ST * 128 * SROWH halves

    const __half* A = USE_MID ? g_mid16 : g_x16;
    const __half* W = g_Wih16 + (size_t)l * G4 * D_DIM;

    const int tid  = threadIdx.x;
    const int lane = tid & 31;
    const int warp = tid >> 5;                   // 0..15
    const int wm   = (warp >> 2) * 64;           // 4 M-warps
    const int wn   = (warp & 3) * 32;            // 4 N-warps
    const int m0   = blockIdx.y * BM;
    const int n0   = blockIdx.x * BN;

    const int a_row  = wm + (lane & 15);
    const int a_koff = (lane >> 4) * 8;
    const int l16    = lane & 15;
    const int b_row  = wn + (l16 & 7);
    const int b_koff = (l16 >> 3) * 8;

    float acc[4][4][4];
#pragma unroll
    for (int im = 0; im < 4; im++)
#pragma unroll
        for (int in = 0; in < 4; in++)
#pragma unroll
            for (int q = 0; q < 4; q++) acc[im][in][q] = 0.0f;

    const uint32_t As_s = (uint32_t)__cvta_generic_to_shared(As);
    const uint32_t Ws_s = (uint32_t)__cvta_generic_to_shared(Ws);

    auto load_stage = [&](int ki, int s) {
#pragma unroll
        for (int i = 0; i < 4; i++) {    // A: 256 rows x 8 cp/row / 512 thr
            int li = tid + i * 512, row = li >> 3, c8 = (li & 7) * 8;
            cp_async16(As_s + (uint32_t)(((s * BM + row) * SROWH + c8) * 2),
                       A + (size_t)(m0 + row) * K_DIM + ki * BK + c8);
        }
#pragma unroll
        for (int i = 0; i < 2; i++) {    // W: 128 rows x 8 cp/row / 512 thr
            int li = tid + i * 512, row = li >> 3, c8 = (li & 7) * 8;
            cp_async16(Ws_s + (uint32_t)(((s * BN + row) * SROWH + c8) * 2),
                       W + (size_t)(n0 + row) * K_DIM + ki * BK + c8);
        }
    };

    load_stage(0, 0); cp_commit();
    load_stage(1, 1); cp_commit();

    // one sync per k-block; wait<1> leaves only the newest group pending
    for (int k = 0; k < NK; k++) {
        cp_wait<1>();
        __syncthreads();

        if (k + 2 < NK) load_stage(k + 2, (k + 2) % ST);

        const uint32_t as_s = As_s + (uint32_t)((k % ST) * BM * SROWH * 2);
        const uint32_t ws_s = Ws_s + (uint32_t)((k % ST) * BN * SROWH * 2);
#pragma unroll
        for (int ks = 0; ks < BK; ks += 16) {
            uint32_t af[4][4];
            uint32_t bf[4][2];
#pragma unroll
            for (int im = 0; im < 4; im++)
                ldsm_x4(af[im][0], af[im][1], af[im][2], af[im][3],
                        as_s + (uint32_t)((((a_row + im * 16) * SROWH) + ks + a_koff) * 2));
#pragma unroll
            for (int in = 0; in < 4; in++)
                ldsm_x2(bf[in][0], bf[in][1],
                        ws_s + (uint32_t)((((b_row + in * 8) * SROWH) + ks + b_koff) * 2));
#pragma unroll
            for (int im = 0; im < 4; im++)
#pragma unroll
                for (int in = 0; in < 4; in++)
                    mma_f16(acc[im][in],
                            af[im][0], af[im][1], af[im][2], af[im][3],
                            bf[in][0], bf[in][1]);
        }
        cp_commit();   // one group per iteration (empty in tail)
    }

    const int wme = wm + (lane >> 2);
    const int wne = wn + (lane & 3) * 2;
#pragma unroll
    for (int im = 0; im < 4; im++)
#pragma unroll
        for (int in = 0; in < 4; in++) {
            int r0 = m0 + wme + im * 16;
            int r1 = r0 + 8;
            int c  = n0 + wne + in * 8;
            g_G[(size_t)r0 * G4 + c]     = acc[im][in][0] + g_FB[(size_t)(r0 & 255) * G4 + c];
            g_G[(size_t)r0 * G4 + c + 1] = acc[im][in][1] + g_FB[(size_t)(r0 & 255) * G4 + c + 1];
            g_G[(size_t)r1 * G4 + c]     = acc[im][in][2] + g_FB[(size_t)(r1 & 255) * G4 + c];
            g_G[(size_t)r1 * G4 + c + 1] = acc[im][in][3] + g_FB[(size_t)(r1 & 255) * G4 + c + 1];
        }
}

// ---------------------------------------------------------------------------
// Per-group barrier (32 CTAs sharing an m0 tile)
// ---------------------------------------------------------------------------
__device__ __forceinline__ void group_barrier(int grp, unsigned r) {
    __syncthreads();
    if (threadIdx.x == 0) {
        __threadfence();
        unsigned prev = atomicAdd(&g_bar_cnt[grp], 1u);
        if (prev + 1u == r * NCTA_GRP) {
            atomicExch(&g_bar_gen[grp], r);
        } else {
            while (*((volatile unsigned*)&g_bar_gen[grp]) < r) { __nanosleep(32); }
        }
        __threadfence();
    }
    __syncthreads();
}

// ---------------------------------------------------------------------------
// Persistent recurrent kernel (UNCHANGED from round 12 -- passing config).
// Grid = (32 j0, 4 m0) = 128 CTAs. BK=128, ST=3, one sync per k-block.
// W of t+1 prefetched pre-barrier; h,c in registers across all 64 steps.
// ---------------------------------------------------------------------------
template <bool LAST_LAYER>
__global__ __launch_bounds__(256) void persistent_step_kernel(
        int l,
        const int* __restrict__ length,
        float* __restrict__ out) {
    constexpr int BM = 64, BN = 128, BK = 128, NK = K_DIM / BK, ST = 3;
    extern __shared__ __half smem_h[];
    __half* As = smem_h;                        // ST * 64 * SROWS halves
    __half* Ws = smem_h + ST * BM * SROWS;      // ST * 128 * SROWS halves
    float (*sg)[BN + 4] = (float(*)[BN + 4])smem_h;   // aliases the As region only

    const __half* __restrict__ Whh16_l = g_Whh16 + (size_t)l * G4 * H_DIM;

    const int tid  = threadIdx.x;
    const int lane = tid & 31;
    const int warp = tid >> 5;
    const int grp  = blockIdx.y;
    const int m0   = grp * BM;
    const int j0   = blockIdx.x * 32;
    const int wm   = (warp >> 2) * (BM / 2);
    const int wn   = (warp & 3) * (BN / 4);

    const int a_row  = wm + (lane & 15);
    const int a_koff = (lane >> 4) * 8;
    const int l16    = lane & 15;
    const int b_row  = wn + (l16 & 7);
    const int b_koff = (l16 >> 3) * 8;

    const uint32_t As_s = (uint32_t)__cvta_generic_to_shared(As);
    const uint32_t Ws_s = (uint32_t)__cvta_generic_to_shared(Ws);

    const int is64 = g_len_is64;
    int   len8[8];
    float hreg[8], creg[8];
#pragma unroll
    for (int it = 0; it < 8; it++) {
        int b = m0 + ((tid + it * 256) >> 5);
        len8[it] = is64 ? length[2 * b] : length[b];
        hreg[it] = 0.0f;
        creg[it] = 0.0f;
    }

    int er0[2], ecl[4];
    size_t ecol[4];
#pragma unroll
    for (int im = 0; im < 2; im++) er0[im] = wm + im * 16 + (lane >> 2);
#pragma unroll
    for (int in = 0; in < 4; in++) {
        ecl[in]  = wn + in * 8 + (lane & 3) * 2;
        ecol[in] = ((size_t)(ecl[in] >> 5) << 10) + j0 + (ecl[in] & 31);
    }

    auto load_W = [&](int ki, int s) {
#pragma unroll
        for (int i = 0; i < 8; i++) {
            int li = tid + i * 256, row = li >> 4, c8 = (li & 15) * 8;
            int wr = ((row >> 5) << 10) + j0 + (row & 31);
            cp_async16(Ws_s + (uint32_t)(((s * BN + row) * SROWS + c8) * 2),
                       Whh16_l + (size_t)wr * H_DIM + ki * BK + c8);
        }
    };
    auto load_A = [&](const __half* h16r, int ki, int s) {
#pragma unroll
        for (int i = 0; i < 4; i++) {
            int li = tid + i * 256, row = li >> 4, c8 = (li & 15) * 8;
            cp_async16(As_s + (uint32_t)(((s * BM + row) * SROWS + c8) * 2),
                       h16r + (size_t)(m0 + row) * H_DIM + ki * BK + c8);
        }
    };
    auto prefetch_G = [&](int t, float gpre[2][4][4]) {
        const size_t gbase = (size_t)t * B_DIM * G4;
#pragma unroll
        for (int im = 0; im < 2; im++)
#pragma unroll
            for (int in = 0; in < 4; in++) {
                const float* gp0 = &g_G[gbase + (size_t)(m0 + er0[im]) * G4 + ecol[in]];
                const float* gp1 = &g_G[gbase + (size_t)(m0 + er0[im] + 8) * G4 + ecol[in]];
                gpre[im][in][0] = __ldcg(gp0);
                gpre[im][in][1] = __ldcg(gp0 + 1);
                gpre[im][in][2] = __ldcg(gp1);
                gpre[im][in][3] = __ldcg(gp1 + 1);
            }
    };

    float gpre[2][4][4];
    load_W(0, 0); cp_commit();
    load_W(1, 1); cp_commit();
    prefetch_G(0, gpre);
    {
        const __half* h0 = g_h16[0];
        load_A(h0, 0, 0); cp_commit();
        load_A(h0, 1, 1); cp_commit();
    }

    for (int t = 0; t < T_DIM; t++) {
        const __half* __restrict__ h16r = g_h16[t & 1];
        __half* __restrict__ h16w = g_h16[(t + 1) & 1];

        float acc[2][4][4];
#pragma unroll
        for (int im = 0; im < 2; im++)
#pragma unroll
            for (int in = 0; in < 4; in++)
#pragma unroll
                for (int q = 0; q < 4; q++) acc[im][in][q] = 0.0f;

#pragma unroll
        for (int k = 0; k < NK; k++) {
            cp_wait<1>();
            __syncthreads();

            if (k + 2 < NK) { load_W(k + 2, (k + 2) % ST); load_A(h16r, k + 2, (k + 2) % ST); }

            const uint32_t as_s = As_s + (uint32_t)((k % ST) * BM * SROWS * 2);
            const uint32_t ws_s = Ws_s + (uint32_t)((k % ST) * BN * SROWS * 2);
#pragma unroll
            for (int ks = 0; ks < BK; ks += 16) {
                uint32_t af[2][4];
                uint32_t bf[4][2];
#pragma unroll
                for (int im = 0; im < 2; im++)
                    ldsm_x4(af[im][0], af[im][1], af[im][2], af[im][3],
                            as_s + (uint32_t)((((a_row + im * 16) * SROWS) + ks + a_koff) * 2));
#pragma unroll
                for (int in = 0; in < 4; in++)
                    ldsm_x2(bf[in][0], bf[in][1],
                            ws_s + (uint32_t)((((b_row + in * 8) * SROWS) + ks + b_koff) * 2));
#pragma unroll
                for (int im = 0; im < 2; im++)
#pragma unroll
                    for (int in = 0; in < 4; in++)
                        mma_f16(acc[im][in],
                                af[im][0], af[im][1], af[im][2], af[im][3],
                                bf[in][0], bf[in][1]);
            }
            cp_commit();
        }
        __syncthreads();

        if (t + 1 < T_DIM) {
            load_W(0, 0); cp_commit();
            load_W(1, 1); cp_commit();
        }

#pragma unroll
        for (int im = 0; im < 2; im++)
#pragma unroll
            for (int in = 0; in < 4; in++) {
                int r0 = er0[im];
                int r1 = r0 + 8;
                int cl = ecl[in];
                sg[r0][cl]     = acc[im][in][0] + gpre[im][in][0];
                sg[r0][cl + 1] = acc[im][in][1] + gpre[im][in][1];
                sg[r1][cl]     = acc[im][in][2] + gpre[im][in][2];
                sg[r1][cl + 1] = acc[im][in][3] + gpre[im][in][3];
            }
        __syncthreads();

#pragma unroll
        for (int it = 0; it < 8; it++) {
            int idx = tid + it * 256;
            int bl  = idx >> 5;
            int jl  = idx & 31;
            float gi = sg[bl][jl];
            float gf = sg[bl][32 + jl];
            float gg = sg[bl][64 + jl];
            float go = sg[bl][96 + jl];

            float c_new = sigf(gf) * creg[it] + sigf(gi) * tanhf(gg);
            float h_new = sigf(go) * tanhf(c_new);

            bool keep = (t < len8[it]);
            float h = keep ? h_new : hreg[it];
            float c = keep ? c_new : creg[it];
            hreg[it] = h;
            creg[it] = c;

            size_t hidx = (size_t)(m0 + bl) * H_DIM + j0 + jl;
            h16w[hidx] = __float2half_rn(h);
            if (LAST_LAYER)
                out[(size_t)t * B_DIM * H_DIM + hidx] = h;
            else
                g_mid16[(size_t)t * B_DIM * H_DIM + hidx] = __float2half_rn(h);
        }
        __syncthreads();

        if (t + 1 < T_DIM) {
            prefetch_G(t + 1, gpre);
            group_barrier(grp, (unsigned)(t + 1));
            load_A(h16w, 0, 0); cp_commit();
            load_A(h16w, 1, 1); cp_commit();
        } else {
            const size_t OUT_MAIN = (size_t)T_DIM * B_DIM * H_DIM;
#pragma unroll
            for (int it = 0; it < 8; it++) {
                int idx = tid + it * 256;
                size_t hidx = (size_t)(m0 + (idx >> 5)) * H_DIM + j0 + (idx & 31);
                out[OUT_MAIN + (size_t)l * B_DIM * H_DIM + hidx]           = hreg[it];
                out[OUT_MAIN + (size_t)(L_DIM + l) * B_DIM * H_DIM + hidx] = creg[it];
            }
        }
    }
}

// ---------------------------------------------------------------------------
// state init (h16 buffer 0 + barrier counters)
// ---------------------------------------------------------------------------
__global__ __launch_bounds__(256) void init_state_kernel() {
    const int idx = blockIdx.x * 256 + threadIdx.x;
    if (idx < B_DIM * H_DIM) {
        g_h16[0][idx] = __float2half_rn(0.0f);
    }
    if (idx < NGRP) {
        g_bar_cnt[idx] = 0u;
        g_bar_gen[idx] = 0u;
    }
}

// ---------------------------------------------------------------------------
// kernel_launch
// inputs: x, features, Wih, Whh, Wfh, b, length
// output: [ out (T,B,H) | h_n (L,B,H) | c_n (L,B,H) ]  fp32
// ---------------------------------------------------------------------------
extern "C" void kernel_launch(void* const* d_in, const int* in_sizes, int n_in,
                              void* d_out, int out_size) {
    (void)in_sizes; (void)n_in; (void)out_size;
    const float* x        = (const float*)d_in[0];
    const float* features = (const float*)d_in[1];
    const float* Wih      = (const float*)d_in[2];
    const float* Whh      = (const float*)d_in[3];
    const float* Wfh      = (const float*)d_in[4];
    const float* bias     = (const float*)d_in[5];
    const int*   length   = (const int*)d_in[6];
    float*       out      = (float*)d_out;

    const dim3 blk(256);
    const dim3 grid_fb(G4 / 128, B_DIM / 64);             // 32 x 4
    const dim3 grid_g(G4 / 128, (T_DIM * B_DIM) / 256);   // 32 x 64 = 2048 CTAs
    const dim3 grid_step(H_DIM / 32, B_DIM / 64);         // 32 x 4 = 128 CTAs
    const int  pw_blocks = (B_DIM * H_DIM) / 256;

    const int FB_SMEM   = 2 * (64 + 128) * SROWH * 2;     // 55296 B
    const int G_SMEM    = 3 * (256 + 128) * SROWH * 2;    // 165888 B
    const int STEP_SMEM = 3 * (64 + 128) * SROWS * 2;     // 156672 B

    static bool attr_done = false;
    if (!attr_done) {
        cudaFuncSetAttribute(fb_kernel, cudaFuncAttributeMaxDynamicSharedMemorySize, FB_SMEM);
        cudaFuncSetAttribute(g_kernel<false>, cudaFuncAttributeMaxDynamicSharedMemorySize, G_SMEM);
        cudaFuncSetAttribute(g_kernel<true>, cudaFuncAttributeMaxDynamicSharedMemorySize, G_SMEM);
        cudaFuncSetAttribute(persistent_step_kernel<false>,
                             cudaFuncAttributeMaxDynamicSharedMemorySize, STEP_SMEM);
        cudaFuncSetAttribute(persistent_step_kernel<true>,
                             cudaFuncAttributeMaxDynamicSharedMemorySize, STEP_SMEM);
        attr_done = true;
    }

    // ---- per-call fp32 -> fp16 conversions (dst chosen by id, device-side) ----
    {
        const size_t nx = (size_t)T_DIM * B_DIM * D_DIM / 4;
        const size_t nf = (size_t)B_DIM * F_DIM / 4;
        const size_t nw = (size_t)L_DIM * G4 * K_DIM / 4;
        cvt_f16_kernel<<<2048, blk>>>(x,        0, nx);
        cvt_f16_kernel<<<256,  blk>>>(features, 1, nf);
        cvt_f16_kernel<<<2048, blk>>>(Wih,      2, nw);
        cvt_f16_kernel<<<2048, blk>>>(Whh,      3, nw);
        cvt_f16_kernel<<<2048, blk>>>(Wfh,      4, nw);
    }

    detect_len_kernel<<<1, 32>>>(length);

    for (int l = 0; l < L_DIM; l++) {
        const float* b_l = bias + (size_t)l * G4;

        init_state_kernel<<<pw_blocks, blk>>>();
        fb_kernel<<<grid_fb, blk, FB_SMEM>>>(l, b_l);
        if (l == 0)
            g_kernel<false><<<grid_g, dim3(512), G_SMEM>>>(l);
        else
            g_kernel<true><<<grid_g, dim3(512), G_SMEM>>>(l);

        if (l == L_DIM - 1)
            persistent_step_kernel<true><<<grid_step, blk, STEP_SMEM>>>(l, length, out);
        else
            persistent_step_kernel<false><<<grid_step, blk, STEP_SMEM>>>(l, length, out);
    }
}

// round 14
// speedup vs baseline: 1.1143x; 1.1143x over previous
#include <cuda_runtime.h>
#include <cuda_fp16.h>
#include <cstdint>
#include <cstddef>

// Problem dims (fixed by the reference)
#define T_DIM 64
#define B_DIM 256
#define D_DIM 1024
#define H_DIM 1024
#define F_DIM 1024
#define L_DIM 2
#define K_DIM 1024
#define G4    (4 * H_DIM)
#define NGRP  4                // independent barrier groups (one per m0 tile)
#define NCTA_GRP 32            // CTAs per group (j0 slices)

#define SROWH 72               // smem row stride in halves (BK=64 + pad 8)  [projections]
#define SROWS 136              // smem row stride in halves (BK=128 + pad 8) [step kernel]

// ---------------------------------------------------------------------------
// Scratch (device globals -- allocation-free per harness rules).
// NEVER pass these as kernel args from host (host sees the shadow symbol; ATS
// makes that silently "work" while the device reads zeros). Device-side only.
// ---------------------------------------------------------------------------
__device__ __half g_G[(size_t)T_DIM * B_DIM * G4];       // pregates, fp16 (134 MB)
__device__ float  g_FB[(size_t)B_DIM * G4];              // features @ Wfh^T + b
__device__ float  g_hbuf[2][(size_t)B_DIM * H_DIM];      // fp32 hidden (mask/output)
__device__ float  g_c[(size_t)B_DIM * H_DIM];            // cell state
__device__ __half g_h16[2][(size_t)B_DIM * H_DIM];       // fp16 hidden (mma operand)
__device__ __half g_mid16[(size_t)T_DIM * B_DIM * H_DIM];// layer-0 outputs (fp16)
__device__ __half g_x16[(size_t)T_DIM * B_DIM * D_DIM];  // x in fp16
__device__ __half g_feat16[(size_t)B_DIM * F_DIM];
__device__ __half g_Wih16[(size_t)L_DIM * G4 * D_DIM];
__device__ __half g_Whh16[(size_t)L_DIM * G4 * H_DIM];
__device__ __half g_Wfh16[(size_t)L_DIM * G4 * F_DIM];
__device__ int    g_len_is64;
__device__ unsigned g_bar_cnt[NGRP];                     // per-group barrier
__device__ unsigned g_bar_gen[NGRP];

// ---------------------------------------------------------------------------
// helpers
// ---------------------------------------------------------------------------
__device__ __forceinline__ void mma_f16(float c[4],
                                        uint32_t a0, uint32_t a1, uint32_t a2, uint32_t a3,
                                        uint32_t b0, uint32_t b1) {
    asm volatile(
        "mma.sync.aligned.m16n8k16.row.col.f32.f16.f16.f32 "
        "{%0,%1,%2,%3}, {%4,%5,%6,%7}, {%8,%9}, {%0,%1,%2,%3};"
        : "+f"(c[0]), "+f"(c[1]), "+f"(c[2]), "+f"(c[3])
        : "r"(a0), "r"(a1), "r"(a2), "r"(a3), "r"(b0), "r"(b1));
}

__device__ __forceinline__ void ldsm_x4(uint32_t& r0, uint32_t& r1,
                                        uint32_t& r2, uint32_t& r3, uint32_t addr) {
    asm volatile("ldmatrix.sync.aligned.m8n8.x4.shared.b16 {%0,%1,%2,%3}, [%4];"
                 : "=r"(r0), "=r"(r1), "=r"(r2), "=r"(r3) : "r"(addr));
}
__device__ __forceinline__ void ldsm_x2(uint32_t& r0, uint32_t& r1, uint32_t addr) {
    asm volatile("ldmatrix.sync.aligned.m8n8.x2.shared.b16 {%0,%1}, [%2];"
                 : "=r"(r0), "=r"(r1) : "r"(addr));
}

__device__ __forceinline__ float sigf(float x) { return 1.0f / (1.0f + __expf(-x)); }

__device__ __forceinline__ void cp_async16(uint32_t saddr, const void* g) {
    asm volatile("cp.async.cg.shared.global [%0], [%1], 16;" :: "r"(saddr), "l"(g));
}
__device__ __forceinline__ void cp_commit() { asm volatile("cp.async.commit_group;"); }
template <int N>
__device__ __forceinline__ void cp_wait() { asm volatile("cp.async.wait_group %0;" :: "n"(N)); }

__device__ __forceinline__ __half2 ldcg_h2(const __half* p) {
    uint32_t v;
    asm volatile("ld.global.cg.b32 %0, [%1];" : "=r"(v) : "l"(p));
    return *reinterpret_cast<__half2*>(&v);
}

// ---------------------------------------------------------------------------
// fp32 -> fp16 conversion. dst selected BY ID; pointer resolved in device code.
// ---------------------------------------------------------------------------
__global__ __launch_bounds__(256) void cvt_f16_kernel(const float* __restrict__ s,
                                                      int dst_id, size_t n4) {
    __half* d;
    switch (dst_id) {
        case 0: d = g_x16;    break;
        case 1: d = g_feat16; break;
        case 2: d = g_Wih16;  break;
        case 3: d = g_Whh16;  break;
        default: d = g_Wfh16; break;
    }
    __half2* d2 = reinterpret_cast<__half2*>(d);
    for (size_t i = blockIdx.x * 256ull + threadIdx.x; i < n4;
         i += (size_t)gridDim.x * 256ull) {
        float4 v = reinterpret_cast<const float4*>(s)[i];
        d2[i * 2]     = __floats2half2_rn(v.x, v.y);
        d2[i * 2 + 1] = __floats2half2_rn(v.z, v.w);
    }
}

// ---------------------------------------------------------------------------
// fp16 cp.async GEMM core, BK=64, ST stages (projection kernels):
// C[BM x BN] = A[m0:,:K] * W[n0:,:K]^T.  A, W row-major fp16 (ld = K_DIM).
// Fragments fed via ldmatrix (x4 for A, x2 for B).
// ---------------------------------------------------------------------------
template <int BM, int BN, int ST>
__device__ __forceinline__ void gemm_core_h(const __half* __restrict__ A,
                                            const __half* __restrict__ W,
                                            int m0, int n0,
                                            float acc[BM / 32][BN / 32][4],
                                            __half* As, __half* Ws) {
    constexpr int BK = 64;
    constexpr int NK = K_DIM / BK;
    constexpr int MI = BM / 32;
    constexpr int NI = BN / 32;

    const int tid  = threadIdx.x;
    const int lane = tid & 31;
    const int warp = tid >> 5;
    const int wm   = (warp >> 2) * (BM / 2);
    const int wn   = (warp & 3) * (BN / 4);

    const int a_row  = wm + (lane & 15);
    const int a_koff = (lane >> 4) * 8;
    const int l16    = lane & 15;
    const int b_row  = wn + (l16 & 7);
    const int b_koff = (l16 >> 3) * 8;

#pragma unroll
    for (int im = 0; im < MI; im++)
#pragma unroll
        for (int in = 0; in < NI; in++)
#pragma unroll
            for (int q = 0; q < 4; q++) acc[im][in][q] = 0.0f;

    const uint32_t As_s = (uint32_t)__cvta_generic_to_shared(As);
    const uint32_t Ws_s = (uint32_t)__cvta_generic_to_shared(Ws);

    auto load_stage = [&](int ki, int s) {
#pragma unroll
        for (int i = 0; i < BM / 32; i++) {
            int li = tid + i * 256, row = li >> 3, c8 = (li & 7) * 8;
            cp_async16(As_s + (uint32_t)(((s * BM + row) * SROWH + c8) * 2),
                       A + (size_t)(m0 + row) * K_DIM + ki * BK + c8);
        }
#pragma unroll
        for (int i = 0; i < BN / 32; i++) {
            int li = tid + i * 256, row = li >> 3, c8 = (li & 7) * 8;
            cp_async16(Ws_s + (uint32_t)(((s * BN + row) * SROWH + c8) * 2),
                       W + (size_t)(n0 + row) * K_DIM + ki * BK + c8);
        }
    };

#pragma unroll
    for (int s = 0; s < ST - 1; s++) { load_stage(s, s); cp_commit(); }

    for (int k = 0; k < NK; k++) {
        if (k + ST - 1 < NK) load_stage(k + ST - 1, (k + ST - 1) % ST);
        cp_commit();
        cp_wait<ST - 1>();
        __syncthreads();

        const uint32_t as_s = As_s + (uint32_t)((k % ST) * BM * SROWH * 2);
        const uint32_t ws_s = Ws_s + (uint32_t)((k % ST) * BN * SROWH * 2);
#pragma unroll
        for (int ks = 0; ks < BK; ks += 16) {
            uint32_t af[MI][4];
            uint32_t bf[NI][2];
#pragma unroll
            for (int im = 0; im < MI; im++)
                ldsm_x4(af[im][0], af[im][1], af[im][2], af[im][3],
                        as_s + (uint32_t)((((a_row + im * 16) * SROWH) + ks + a_koff) * 2));
#pragma unroll
            for (int in = 0; in < NI; in++)
                ldsm_x2(bf[in][0], bf[in][1],
                        ws_s + (uint32_t)((((b_row + in * 8) * SROWH) + ks + b_koff) * 2));
#pragma unroll
            for (int im = 0; im < MI; im++)
#pragma unroll
                for (int in = 0; in < NI; in++)
                    mma_f16(acc[im][in],
                            af[im][0], af[im][1], af[im][2], af[im][3],
                            bf[in][0], bf[in][1]);
        }
        __syncthreads();
    }
}

// ---------------------------------------------------------------------------
// length dtype probe
// ---------------------------------------------------------------------------
__global__ void detect_len_kernel(const int* __restrict__ L) {
    if (threadIdx.x == 0) {
        int any = 0;
        for (int i = 1; i < 256; i += 2) any |= L[i];
        g_len_is64 = (any == 0) ? 1 : 0;
    }
}

// ---------------------------------------------------------------------------
// FB = features @ Wfh_l^T + b_l      (M=256, N=4096)
// ---------------------------------------------------------------------------
__global__ __launch_bounds__(256, 2) void fb_kernel(int l, const float* __restrict__ bias_l) {
    constexpr int BM = 64, BN = 128, ST = 2;
    extern __shared__ __half smem_h[];
    __half* As = smem_h;
    __half* Ws = smem_h + ST * BM * SROWH;

    const __half* Wfh16_l = g_Wfh16 + (size_t)l * G4 * F_DIM;

    float acc[BM / 32][BN / 32][4];
    const int m0 = blockIdx.y * BM;
    const int n0 = blockIdx.x * BN;
    gemm_core_h<BM, BN, ST>(g_feat16, Wfh16_l, m0, n0, acc, As, Ws);

    const int lane = threadIdx.x & 31, warp = threadIdx.x >> 5;
    const int wm = (warp >> 2) * (BM / 2) + (lane >> 2);
    const int wn = (warp & 3) * (BN / 4) + (lane & 3) * 2;
#pragma unroll
    for (int im = 0; im < BM / 32; im++)
#pragma unroll
        for (int in = 0; in < BN / 32; in++) {
            int r0 = m0 + wm + im * 16;
            int c  = n0 + wn + in * 8;
            g_FB[(size_t)r0 * G4 + c]           = acc[im][in][0] + bias_l[c];
            g_FB[(size_t)r0 * G4 + c + 1]       = acc[im][in][1] + bias_l[c + 1];
            g_FB[(size_t)(r0 + 8) * G4 + c]     = acc[im][in][2] + bias_l[c];
            g_FB[(size_t)(r0 + 8) * G4 + c + 1] = acc[im][in][3] + bias_l[c + 1];
        }
}

// ---------------------------------------------------------------------------
// G = inp @ Wih_l^T + FB[b]   (M=16384, N=4096);  b = row & 255.
// Round-11 config (best): BM=128, BN=128, 256 thr, ST=2, 2 CTAs/SM.
// NEW: G stored as fp16 (__half2 stores; halves the DRAM write traffic).
// ---------------------------------------------------------------------------
template <bool USE_MID>
__global__ __launch_bounds__(256, 2) void g_kernel(int l) {
    constexpr int BM = 128, BN = 128, ST = 2;
    extern __shared__ __half smem_h[];
    __half* As = smem_h;
    __half* Ws = smem_h + ST * BM * SROWH;

    const __half* inp     = USE_MID ? g_mid16 : g_x16;
    const __half* Wih16_l = g_Wih16 + (size_t)l * G4 * D_DIM;

    float acc[BM / 32][BN / 32][4];
    const int m0 = blockIdx.y * BM;
    const int n0 = blockIdx.x * BN;
    gemm_core_h<BM, BN, ST>(inp, Wih16_l, m0, n0, acc, As, Ws);

    const int lane = threadIdx.x & 31, warp = threadIdx.x >> 5;
    const int wm = (warp >> 2) * (BM / 2) + (lane >> 2);
    const int wn = (warp & 3) * (BN / 4) + (lane & 3) * 2;
#pragma unroll
    for (int im = 0; im < BM / 32; im++)
#pragma unroll
        for (int in = 0; in < BN / 32; in++) {
            int r0 = m0 + wm + im * 16;
            int r1 = r0 + 8;
            int c  = n0 + wn + in * 8;
            float s00 = acc[im][in][0] + g_FB[(size_t)(r0 & 255) * G4 + c];
            float s01 = acc[im][in][1] + g_FB[(size_t)(r0 & 255) * G4 + c + 1];
            float s10 = acc[im][in][2] + g_FB[(size_t)(r1 & 255) * G4 + c];
            float s11 = acc[im][in][3] + g_FB[(size_t)(r1 & 255) * G4 + c + 1];
            *reinterpret_cast<__half2*>(&g_G[(size_t)r0 * G4 + c]) = __floats2half2_rn(s00, s01);
            *reinterpret_cast<__half2*>(&g_G[(size_t)r1 * G4 + c]) = __floats2half2_rn(s10, s11);
        }
}

// ---------------------------------------------------------------------------
// Per-group barrier (32 CTAs sharing an m0 tile)
// ---------------------------------------------------------------------------
__device__ __forceinline__ void group_barrier(int grp, unsigned r) {
    __syncthreads();
    if (threadIdx.x == 0) {
        __threadfence();
        unsigned prev = atomicAdd(&g_bar_cnt[grp], 1u);
        if (prev + 1u == r * NCTA_GRP) {
            atomicExch(&g_bar_gen[grp], r);
        } else {
            while (*((volatile unsigned*)&g_bar_gen[grp]) < r) { __nanosleep(32); }
        }
        __threadfence();
    }
    __syncthreads();
}

// ---------------------------------------------------------------------------
// Persistent recurrent kernel (round-11 config -- best passing).
// Grid = (32 j0, 4 m0) = 128 CTAs. BK=128, ST=3, one sync per k-block.
// Epilogue operands (G[t] fp16, h_old, c_old) prefetched into registers
// BEFORE the k-loop; length hoisted outside the t-loop.
// ---------------------------------------------------------------------------
template <bool LAST_LAYER>
__global__ __launch_bounds__(256) void persistent_step_kernel(
        int l,
        const int* __restrict__ length,
        float* __restrict__ out) {
    constexpr int BM = 64, BN = 128, BK = 128, NK = K_DIM / BK, ST = 3;
    extern __shared__ __half smem_h[];
    __half* As = smem_h;                        // ST * 64 * SROWS halves
    __half* Ws = smem_h + ST * BM * SROWS;      // ST * 128 * SROWS halves
    float (*sg)[BN + 4] = (float(*)[BN + 4])smem_h;   // aliases the As region only

    const __half* __restrict__ Whh16_l = g_Whh16 + (size_t)l * G4 * H_DIM;

    const int tid  = threadIdx.x;
    const int lane = tid & 31;
    const int warp = tid >> 5;
    const int grp  = blockIdx.y;        // m0 group id
    const int m0   = grp * BM;          // batch offset
    const int j0   = blockIdx.x * 32;   // hidden-column slice
    const int wm   = (warp >> 2) * (BM / 2);
    const int wn   = (warp & 3) * (BN / 4);

    const int a_row  = wm + (lane & 15);
    const int a_koff = (lane >> 4) * 8;
    const int l16    = lane & 15;
    const int b_row  = wn + (l16 & 7);
    const int b_koff = (l16 >> 3) * 8;

    const uint32_t As_s = (uint32_t)__cvta_generic_to_shared(As);
    const uint32_t Ws_s = (uint32_t)__cvta_generic_to_shared(Ws);

    // ---- t-invariant: per-thread lengths for the 8 cell elements ----
    const int is64 = g_len_is64;
    int len8[8];
#pragma unroll
    for (int it = 0; it < 8; it++) {
        int b = m0 + ((tid + it * 256) >> 5);
        len8[it] = is64 ? length[2 * b] : length[b];
    }

    // ---- t-invariant: epilogue fragment coordinates ----
    int er0[2], ecl[4];
    size_t ecol[4];
#pragma unroll
    for (int im = 0; im < 2; im++) er0[im] = wm + im * 16 + (lane >> 2);
#pragma unroll
    for (int in = 0; in < 4; in++) {
        ecl[in]  = wn + in * 8 + (lane & 3) * 2;
        ecol[in] = ((size_t)(ecl[in] >> 5) << 10) + j0 + (ecl[in] & 31);
    }

    for (int t = 0; t < T_DIM; t++) {
        const __half* __restrict__ h16r = g_h16[t & 1];
        __half* __restrict__ h16w = g_h16[(t + 1) & 1];
        const float* __restrict__ hr32 = g_hbuf[t & 1];
        float* __restrict__ hw32 = g_hbuf[(t + 1) & 1];

        float acc[2][4][4];
#pragma unroll
        for (int im = 0; im < 2; im++)
#pragma unroll
            for (int in = 0; in < 4; in++)
#pragma unroll
                for (int q = 0; q < 4; q++) acc[im][in][q] = 0.0f;

        auto load_stage = [&](int ki, int s) {
#pragma unroll
            for (int i = 0; i < 4; i++) {   // A: 64 rows x 16 cp/row
                int li = tid + i * 256, row = li >> 4, c8 = (li & 15) * 8;
                cp_async16(As_s + (uint32_t)(((s * BM + row) * SROWS + c8) * 2),
                           h16r + (size_t)(m0 + row) * H_DIM + ki * BK + c8);
            }
#pragma unroll
            for (int i = 0; i < 8; i++) {   // W: 128 rows; wr = (row>>5)*1024 + j0 + (row&31)
                int li = tid + i * 256, row = li >> 4, c8 = (li & 15) * 8;
                int wr = ((row >> 5) << 10) + j0 + (row & 31);
                cp_async16(Ws_s + (uint32_t)(((s * BN + row) * SROWS + c8) * 2),
                           Whh16_l + (size_t)wr * H_DIM + ki * BK + c8);
            }
        };

        // ---- prologue: stage 0, epilogue prefetch, stage 1 ----
        load_stage(0, 0); cp_commit();

        const size_t gbase = (size_t)t * B_DIM * G4;
        float gpre[2][4][4];
#pragma unroll
        for (int im = 0; im < 2; im++)
#pragma unroll
            for (int in = 0; in < 4; in++) {
                const __half* gp0 = &g_G[gbase + (size_t)(m0 + er0[im]) * G4 + ecol[in]];
                const __half* gp1 = &g_G[gbase + (size_t)(m0 + er0[im] + 8) * G4 + ecol[in]];
                float2 f0 = __half22float2(ldcg_h2(gp0));
                float2 f1 = __half22float2(ldcg_h2(gp1));
                gpre[im][in][0] = f0.x;
                gpre[im][in][1] = f0.y;
                gpre[im][in][2] = f1.x;
                gpre[im][in][3] = f1.y;
            }
        float hpre[8], cpre[8];
#pragma unroll
        for (int it = 0; it < 8; it++) {
            int idx = tid + it * 256;
            size_t hidx = (size_t)(m0 + (idx >> 5)) * H_DIM + j0 + (idx & 31);
            hpre[it] = __ldcg(&hr32[hidx]);
            cpre[it] = g_c[hidx];
        }

        load_stage(1, 1); cp_commit();

        // ---- k-loop: 3-stage pipeline, ONE sync per block ----
#pragma unroll
        for (int k = 0; k < NK; k++) {
            cp_wait<1>();
            __syncthreads();

            if (k + 2 < NK) load_stage(k + 2, (k + 2) % ST);

            const uint32_t as_s = As_s + (uint32_t)((k % ST) * BM * SROWS * 2);
            const uint32_t ws_s = Ws_s + (uint32_t)((k % ST) * BN * SROWS * 2);
#pragma unroll
            for (int ks = 0; ks < BK; ks += 16) {
                uint32_t af[2][4];
                uint32_t bf[4][2];
#pragma unroll
                for (int im = 0; im < 2; im++)
                    ldsm_x4(af[im][0], af[im][1], af[im][2], af[im][3],
                            as_s + (uint32_t)((((a_row + im * 16) * SROWS) + ks + a_koff) * 2));
#pragma unroll
                for (int in = 0; in < 4; in++)
                    ldsm_x2(bf[in][0], bf[in][1],
                            ws_s + (uint32_t)((((b_row + in * 8) * SROWS) + ks + b_koff) * 2));
#pragma unroll
                for (int im = 0; im < 2; im++)
#pragma unroll
                    for (int in = 0; in < 4; in++)
                        mma_f16(acc[im][in],
                                af[im][0], af[im][1], af[im][2], af[im][3],
                                bf[in][0], bf[in][1]);
            }
            cp_commit();   // one group per iteration (empty in the tail)
        }
        __syncthreads();   // all warps done reading smem before sg overwrite

        // ---- gates -> smem (add prefetched pregates) ----
#pragma unroll
        for (int im = 0; im < 2; im++)
#pragma unroll
            for (int in = 0; in < 4; in++) {
                int r0 = er0[im];
                int r1 = r0 + 8;
                int cl = ecl[in];
                sg[r0][cl]     = acc[im][in][0] + gpre[im][in][0];
                sg[r0][cl + 1] = acc[im][in][1] + gpre[im][in][1];
                sg[r1][cl]     = acc[im][in][2] + gpre[im][in][2];
                sg[r1][cl + 1] = acc[im][in][3] + gpre[im][in][3];
            }
        __syncthreads();

        // ---- LSTM cell + mask: 64 x 32 elements, 8 per thread ----
#pragma unroll
        for (int it = 0; it < 8; it++) {
            int idx = tid + it * 256;
            int bl  = idx >> 5;
            int jl  = idx & 31;
            float gi = sg[bl][jl];
            float gf = sg[bl][32 + jl];
            float gg = sg[bl][64 + jl];
            float go = sg[bl][96 + jl];

            size_t hidx = (size_t)(m0 + bl) * H_DIM + j0 + jl;
            float c_old = cpre[it];
            float h_old = hpre[it];

            float c_new = sigf(gf) * c_old + sigf(gi) * tanhf(gg);
            float h_new = sigf(go) * tanhf(c_new);

            bool keep = (t < len8[it]);
            float h = keep ? h_new : h_old;
            float c = keep ? c_new : c_old;

            hw32[hidx] = h;
            h16w[hidx] = __float2half_rn(h);
            g_c[hidx]  = c;

            if (LAST_LAYER)
                out[(size_t)t * B_DIM * H_DIM + hidx] = h;
            else
                g_mid16[(size_t)t * B_DIM * H_DIM + hidx] = __float2half_rn(h);
        }
        __syncthreads();   // sg reads done before next step's loads overwrite smem

        if (t + 1 < T_DIM) group_barrier(grp, (unsigned)(t + 1));
    }
}

// ---------------------------------------------------------------------------
// state init / final-state copy-out
// ---------------------------------------------------------------------------
__global__ __launch_bounds__(256) void init_state_kernel() {
    const int idx = blockIdx.x * 256 + threadIdx.x;
    if (idx < B_DIM * H_DIM) {
        g_hbuf[0][idx] = 0.0f;
        g_h16[0][idx]  = __float2half_rn(0.0f);
        g_c[idx]       = 0.0f;
    }
    if (idx < NGRP) {
        g_bar_cnt[idx] = 0u;
        g_bar_gen[idx] = 0u;
    }
}

__global__ __launch_bounds__(256) void copy_state_kernel(float* __restrict__ out, int l) {
    const int idx = blockIdx.x * 256 + threadIdx.x;
    if (idx < B_DIM * H_DIM) {
        const size_t OUT_MAIN = (size_t)T_DIM * B_DIM * H_DIM;
        out[OUT_MAIN + (size_t)l * B_DIM * H_DIM + idx]           = g_hbuf[0][idx];
        out[OUT_MAIN + (size_t)(L_DIM + l) * B_DIM * H_DIM + idx] = g_c[idx];
    }
}

// ---------------------------------------------------------------------------
// kernel_launch
// inputs: x, features, Wih, Whh, Wfh, b, length
// output: [ out (T,B,H) | h_n (L,B,H) | c_n (L,B,H) ]  fp32
// ---------------------------------------------------------------------------
extern "C" void kernel_launch(void* const* d_in, const int* in_sizes, int n_in,
                              void* d_out, int out_size) {
    (void)in_sizes; (void)n_in; (void)out_size;
    const float* x        = (const float*)d_in[0];
    const float* features = (const float*)d_in[1];
    const float* Wih      = (const float*)d_in[2];
    const float* Whh      = (const float*)d_in[3];
    const float* Wfh      = (const float*)d_in[4];
    const float* bias     = (const float*)d_in[5];
    const int*   length   = (const int*)d_in[6];
    float*       out      = (float*)d_out;

    const dim3 blk(256);
    const dim3 grid_fb(G4 / 128, B_DIM / 64);             // 32 x 4
    const dim3 grid_g(G4 / 128, (T_DIM * B_DIM) / 128);   // 32 x 128
    const dim3 grid_step(H_DIM / 32, B_DIM / 64);         // 32 x 4 = 128 CTAs
    const int  pw_blocks = (B_DIM * H_DIM) / 256;

    const int FB_SMEM   = 2 * (64 + 128) * SROWH * 2;     // 55296 B
    const int G_SMEM    = 2 * (128 + 128) * SROWH * 2;    // 73728 B
    const int STEP_SMEM = 3 * (64 + 128) * SROWS * 2;     // 156672 B

    static bool attr_done = false;
    if (!attr_done) {
        cudaFuncSetAttribute(fb_kernel, cudaFuncAttributeMaxDynamicSharedMemorySize, FB_SMEM);
        cudaFuncSetAttribute(g_kernel<false>, cudaFuncAttributeMaxDynamicSharedMemorySize, G_SMEM);
        cudaFuncSetAttribute(g_kernel<true>, cudaFuncAttributeMaxDynamicSharedMemorySize, G_SMEM);
        cudaFuncSetAttribute(persistent_step_kernel<false>,
                             cudaFuncAttributeMaxDynamicSharedMemorySize, STEP_SMEM);
        cudaFuncSetAttribute(persistent_step_kernel<true>,
                             cudaFuncAttributeMaxDynamicSharedMemorySize, STEP_SMEM);
        attr_done = true;
    }

    // ---- per-call fp32 -> fp16 conversions (dst chosen by id, device-side) ----
    {
        const size_t nx = (size_t)T_DIM * B_DIM * D_DIM / 4;
        const size_t nf = (size_t)B_DIM * F_DIM / 4;
        const size_t nw = (size_t)L_DIM * G4 * K_DIM / 4;
        cvt_f16_kernel<<<2048, blk>>>(x,        0, nx);
        cvt_f16_kernel<<<256,  blk>>>(features, 1, nf);
        cvt_f16_kernel<<<2048, blk>>>(Wih,      2, nw);
        cvt_f16_kernel<<<2048, blk>>>(Whh,      3, nw);
        cvt_f16_kernel<<<2048, blk>>>(Wfh,      4, nw);
    }

    detect_len_kernel<<<1, 32>>>(length);

    for (int l = 0; l < L_DIM; l++) {
        const float* b_l = bias + (size_t)l * G4;

        init_state_kernel<<<pw_blocks, blk>>>();
        fb_kernel<<<grid_fb, blk, FB_SMEM>>>(l, b_l);
        if (l == 0)
            g_kernel<false><<<grid_g, blk, G_SMEM>>>(l);
        else
            g_kernel<true><<<grid_g, blk, G_SMEM>>>(l);

        if (l == L_DIM - 1)
            persistent_step_kernel<true><<<grid_step, blk, STEP_SMEM>>>(l, length, out);
        else
            persistent_step_kernel<false><<<grid_step, blk, STEP_SMEM>>>(l, length, out);

        copy_state_kernel<<<pw_blocks, blk>>>(out, l);
    }
}